// round 1
// baseline (speedup 1.0000x reference)
#include <cuda_runtime.h>
#include <math.h>

#define BB 2
#define NH 8
#define DH 64
#define DM 512
#define NQ 4096
#define NKK 4096
#define MROWS (BB*NQ)                       // 8192
#define ATTN_ELEMS ((size_t)NH*BB*(size_t)NQ*(size_t)NKK)   // 268435456

// scratch (device globals; no allocation allowed)
__device__ float g_q[BB*NH*NQ*DH];
__device__ float g_k[BB*NH*NKK*DH];
__device__ float g_v[BB*NH*NKK*DH];
__device__ float g_o[MROWS*DM];
__device__ float g_l[BB*NH*NQ];

// ---------------------------------------------------------------------------
// NT GEMM with bias: C[M,512] = A[M,512] @ W[512,512]^T + bias
// split=1: scatter C[i, h*64+d] -> out[b][h][i_local][d]  (head-split layout)
// split=0: plain row-major C
// ---------------------------------------------------------------------------
__global__ __launch_bounds__(256) void gemm_nt(
    const float* __restrict__ A, const float* __restrict__ W,
    const float* __restrict__ bias, float* __restrict__ C, int split)
{
    __shared__ float As[64][17];
    __shared__ float Ws[64][17];

    int i0 = blockIdx.y * 64;
    int j0 = blockIdx.x * 64;
    int tx = threadIdx.x, ty = threadIdx.y;
    int t  = ty * 16 + tx;
    int lr = t >> 2;          // 0..63
    int lk = (t & 3) * 4;     // 0,4,8,12

    float acc[4][4] = {};

    for (int k0 = 0; k0 < DM; k0 += 16) {
        float4 av = *(const float4*)(A + (size_t)(i0 + lr) * DM + k0 + lk);
        float4 wv = *(const float4*)(W + (size_t)(j0 + lr) * DM + k0 + lk);
        As[lr][lk+0]=av.x; As[lr][lk+1]=av.y; As[lr][lk+2]=av.z; As[lr][lk+3]=av.w;
        Ws[lr][lk+0]=wv.x; Ws[lr][lk+1]=wv.y; Ws[lr][lk+2]=wv.z; Ws[lr][lk+3]=wv.w;
        __syncthreads();
        #pragma unroll
        for (int kk = 0; kk < 16; kk++) {
            float a[4], w[4];
            #pragma unroll
            for (int aa = 0; aa < 4; aa++) a[aa] = As[ty*4+aa][kk];
            #pragma unroll
            for (int cc = 0; cc < 4; cc++) w[cc] = Ws[tx*4+cc][kk];
            #pragma unroll
            for (int aa = 0; aa < 4; aa++)
                #pragma unroll
                for (int cc = 0; cc < 4; cc++)
                    acc[aa][cc] += a[aa] * w[cc];
        }
        __syncthreads();
    }

    int j = j0 + tx * 4;
    float4 bv = *(const float4*)(bias + j);
    #pragma unroll
    for (int aa = 0; aa < 4; aa++) {
        int i = i0 + ty * 4 + aa;
        float4 r = make_float4(acc[aa][0]+bv.x, acc[aa][1]+bv.y,
                               acc[aa][2]+bv.z, acc[aa][3]+bv.w);
        if (split) {
            int b = i >> 12, il = i & (NQ-1);
            int h = j >> 6,  d  = j & (DH-1);
            *(float4*)(C + (((size_t)(b*NH + h)*NQ + il)*DH + d)) = r;
        } else {
            *(float4*)(C + (size_t)i * DM + j) = r;
        }
    }
}

// ---------------------------------------------------------------------------
// Fused attention: per (b,h,q-tile of 64): loop k-tiles of 64:
//   S = Q K^T * 0.125 ; P = exp(S) (0 where masked) ; write P (unnormalized,
//   streaming) ; l += rowsum(P) ; O += P V.  End: O /= l, store l.
// ---------------------------------------------------------------------------
__global__ __launch_bounds__(256) void attn_kernel(
    const unsigned char* __restrict__ mask, float* __restrict__ attn)
{
    extern __shared__ float sm[];
    float (*Qs)[64] = (float(*)[64])(sm);
    float (*Ks)[65] = (float(*)[65])(sm + 64*64);
    float (*Vs)[64] = (float(*)[64])(sm + 64*64 + 64*65);
    float (*Ps)[64] = (float(*)[64])(sm + 64*64*2 + 64*65);

    int bh = blockIdx.y;
    int b = bh >> 3, h = bh & 7;
    int i0 = blockIdx.x * 64;
    int tx = threadIdx.x, ty = threadIdx.y;
    int tid = ty * 16 + tx;

    const float* qb = g_q + ((size_t)bh * NQ + i0) * DH;
    for (int idx = tid; idx < 64*64; idx += 256) {
        int r = idx >> 6, d = idx & 63;
        Qs[r][d] = qb[(size_t)r * DH + d];
    }

    float oacc[4][4] = {};
    float lacc[4] = {};
    float* ab = attn + ((size_t)(h * BB + b) * NQ + i0) * NKK;
    const unsigned char* mb = mask + ((size_t)b * NQ + i0) * NKK;

    for (int j0 = 0; j0 < NKK; j0 += 64) {
        __syncthreads();   // protect previous tile's Ps/Vs reads
        const float* kb = g_k + ((size_t)bh * NKK + j0) * DH;
        const float* vb = g_v + ((size_t)bh * NKK + j0) * DH;
        for (int idx = tid; idx < 64*64; idx += 256) {
            int r = idx >> 6, d = idx & 63;
            Ks[r][d] = kb[(size_t)r * DH + d];
            Vs[r][d] = vb[(size_t)r * DH + d];
        }
        __syncthreads();

        float s[4][4] = {};
        #pragma unroll 16
        for (int d = 0; d < 64; d++) {
            float qv[4], kv[4];
            #pragma unroll
            for (int a = 0; a < 4; a++) qv[a] = Qs[ty*4+a][d];
            #pragma unroll
            for (int c = 0; c < 4; c++) kv[c] = Ks[tx*4+c][d];
            #pragma unroll
            for (int a = 0; a < 4; a++)
                #pragma unroll
                for (int c = 0; c < 4; c++)
                    s[a][c] += qv[a] * kv[c];
        }

        #pragma unroll
        for (int a = 0; a < 4; a++) {
            int r = ty * 4 + a;
            uchar4 mv = *(const uchar4*)(mb + (size_t)r * NKK + j0 + tx * 4);
            float p0 = mv.x ? 0.0f : __expf(s[a][0] * 0.125f);
            float p1 = mv.y ? 0.0f : __expf(s[a][1] * 0.125f);
            float p2 = mv.z ? 0.0f : __expf(s[a][2] * 0.125f);
            float p3 = mv.w ? 0.0f : __expf(s[a][3] * 0.125f);
            lacc[a] += (p0 + p1) + (p2 + p3);
            Ps[r][tx*4+0] = p0; Ps[r][tx*4+1] = p1;
            Ps[r][tx*4+2] = p2; Ps[r][tx*4+3] = p3;
            __stcs((float4*)(ab + (size_t)r * NKK + j0 + tx * 4),
                   make_float4(p0, p1, p2, p3));
        }
        __syncthreads();

        #pragma unroll 16
        for (int c = 0; c < 64; c++) {
            float pv[4], vv[4];
            #pragma unroll
            for (int a = 0; a < 4; a++) pv[a] = Ps[ty*4+a][c];
            #pragma unroll
            for (int j = 0; j < 4; j++) vv[j] = Vs[c][tx*4+j];
            #pragma unroll
            for (int a = 0; a < 4; a++)
                #pragma unroll
                for (int j = 0; j < 4; j++)
                    oacc[a][j] += pv[a] * vv[j];
        }
    }

    // reduce row-sums across the 16 tx lanes
    __syncthreads();
    #pragma unroll
    for (int a = 0; a < 4; a++) Ps[ty*4+a][tx] = lacc[a];
    __syncthreads();
    if (tid < 64) {
        float ssum = 0.0f;
        #pragma unroll
        for (int t2 = 0; t2 < 16; t2++) ssum += Ps[tid][t2];
        g_l[(size_t)bh * NQ + i0 + tid] = ssum;
        Ps[tid][16] = 1.0f / ssum;
    }
    __syncthreads();

    #pragma unroll
    for (int a = 0; a < 4; a++) {
        int r = ty * 4 + a;
        float inv = Ps[r][16];
        float4 ov = make_float4(oacc[a][0]*inv, oacc[a][1]*inv,
                                oacc[a][2]*inv, oacc[a][3]*inv);
        *(float4*)(g_o + ((size_t)(b * NQ + i0 + r)) * DM + h * DH + tx * 4) = ov;
    }
}

// ---------------------------------------------------------------------------
// Streaming normalize: attn[h,b,i,:] /= l[b,h,i]
// ---------------------------------------------------------------------------
__global__ __launch_bounds__(256) void norm_attn(float* __restrict__ attn)
{
    size_t idx = (size_t)blockIdx.x * blockDim.x + threadIdx.x;  // float4 index
    size_t row = idx >> 10;           // 1024 float4 per row of 4096
    int i  = (int)(row & (NQ - 1));
    int hb = (int)(row >> 12);        // 0..15, layout [h][b]
    int h = hb >> 1, b = hb & 1;
    float inv = 1.0f / g_l[(size_t)(b * NH + h) * NQ + i];
    float4 v = __ldcs((const float4*)attn + idx);
    v.x *= inv; v.y *= inv; v.z *= inv; v.w *= inv;
    __stcs((float4*)attn + idx, v);
}

extern "C" void kernel_launch(void* const* d_in, const int* in_sizes, int n_in,
                              void* d_out, int out_size)
{
    const float* q  = (const float*)d_in[0];
    const float* k  = (const float*)d_in[1];
    const float* v  = (const float*)d_in[2];
    const unsigned char* mask = (const unsigned char*)d_in[3];
    const float* Wq = (const float*)d_in[4];
    const float* bq = (const float*)d_in[5];
    const float* Wk = (const float*)d_in[6];
    const float* bk = (const float*)d_in[7];
    const float* Wv = (const float*)d_in[8];
    const float* bv = (const float*)d_in[9];
    const float* Wo = (const float*)d_in[10];
    const float* bo = (const float*)d_in[11];

    float* outbuf = (float*)d_out;
    float* attn = outbuf;
    float* outp = outbuf + ATTN_ELEMS;

    float *gq, *gk, *gv, *go;
    cudaGetSymbolAddress((void**)&gq, g_q);
    cudaGetSymbolAddress((void**)&gk, g_k);
    cudaGetSymbolAddress((void**)&gv, g_v);
    cudaGetSymbolAddress((void**)&go, g_o);

    dim3 blk(16, 16);
    dim3 gproj(DM / 64, MROWS / 64);

    gemm_nt<<<gproj, blk>>>(q, Wq, bq, gq, 1);
    gemm_nt<<<gproj, blk>>>(k, Wk, bk, gk, 1);
    gemm_nt<<<gproj, blk>>>(v, Wv, bv, gv, 1);

    const int smem_bytes = (64*64*3 + 64*65) * 4;   // 65792
    cudaFuncSetAttribute(attn_kernel,
        cudaFuncAttributeMaxDynamicSharedMemorySize, smem_bytes);
    attn_kernel<<<dim3(NQ / 64, BB * NH), blk, smem_bytes>>>(mask, attn);

    norm_attn<<<(unsigned)(ATTN_ELEMS / 4 / 256), 256>>>(attn);

    gemm_nt<<<gproj, blk>>>(go, Wo, bo, outp, 0);
}

// round 3
// speedup vs baseline: 1.5387x; 1.5387x over previous
#include <cuda_runtime.h>
#include <math.h>
#include <stdint.h>

#define BB 2
#define NH 8
#define DH 64
#define DM 512
#define NQ 4096
#define NKK 4096
#define MROWS (BB*NQ)                       // 8192
#define ATTN_ELEMS ((size_t)NH*BB*(size_t)NQ*(size_t)NKK)   // 268435456

// scratch (device globals; no allocation allowed)
__device__ float g_q[BB*NH*NQ*DH];
__device__ float g_k[BB*NH*NKK*DH];
__device__ float g_v[BB*NH*NKK*DH];
__device__ float g_o[MROWS*DM];
__device__ float g_l[BB*NH*NQ];

// ===========================================================================
// helpers
// ===========================================================================
__device__ __forceinline__ uint32_t s2u(const void* p){
    uint32_t a;
    asm("{ .reg .u64 t; cvta.to.shared.u64 t, %1; cvt.u32.u64 %0, t; }"
        : "=r"(a) : "l"(p));
    return a;
}
__device__ __forceinline__ uint32_t f2tf(float f){
    uint32_t u; asm("cvt.rna.tf32.f32 %0, %1;" : "=r"(u) : "f"(f)); return u;
}
__device__ __forceinline__ void mma8(float* d, const uint32_t* a,
                                     uint32_t b0, uint32_t b1){
    asm volatile("mma.sync.aligned.m16n8k8.row.col.f32.tf32.tf32.f32 "
        "{%0,%1,%2,%3}, {%4,%5,%6,%7}, {%8,%9}, {%0,%1,%2,%3};"
        : "+f"(d[0]), "+f"(d[1]), "+f"(d[2]), "+f"(d[3])
        : "r"(a[0]), "r"(a[1]), "r"(a[2]), "r"(a[3]), "r"(b0), "r"(b1));
}
__device__ __forceinline__ void cpa16(uint32_t s, const void* g){
    asm volatile("cp.async.cg.shared.global [%0], [%1], 16;" :: "r"(s), "l"(g));
}
#define CP_COMMIT() asm volatile("cp.async.commit_group;" ::: "memory")
#define CP_WAIT(n)  asm volatile("cp.async.wait_group %0;" :: "n"(n) : "memory")

// ===========================================================================
// NT GEMM with bias: C[M,512] = A[M,512] @ W[512,512]^T + bias
// split=1: head-split [bh][n][d]; split=0: plain row-major
// ===========================================================================
__global__ __launch_bounds__(256) void gemm_nt(
    const float* __restrict__ A, const float* __restrict__ W,
    const float* __restrict__ bias, float* __restrict__ C, int split)
{
    __shared__ float As[64][17];
    __shared__ float Ws[64][17];

    int i0 = blockIdx.y * 64;
    int j0 = blockIdx.x * 64;
    int tx = threadIdx.x, ty = threadIdx.y;
    int t  = ty * 16 + tx;
    int lr = t >> 2;
    int lk = (t & 3) * 4;

    float acc[4][4] = {};

    for (int k0 = 0; k0 < DM; k0 += 16) {
        float4 av = *(const float4*)(A + (size_t)(i0 + lr) * DM + k0 + lk);
        float4 wv = *(const float4*)(W + (size_t)(j0 + lr) * DM + k0 + lk);
        As[lr][lk+0]=av.x; As[lr][lk+1]=av.y; As[lr][lk+2]=av.z; As[lr][lk+3]=av.w;
        Ws[lr][lk+0]=wv.x; Ws[lr][lk+1]=wv.y; Ws[lr][lk+2]=wv.z; Ws[lr][lk+3]=wv.w;
        __syncthreads();
        #pragma unroll
        for (int kk = 0; kk < 16; kk++) {
            float a[4], w[4];
            #pragma unroll
            for (int aa = 0; aa < 4; aa++) a[aa] = As[ty*4+aa][kk];
            #pragma unroll
            for (int cc = 0; cc < 4; cc++) w[cc] = Ws[tx*4+cc][kk];
            #pragma unroll
            for (int aa = 0; aa < 4; aa++)
                #pragma unroll
                for (int cc = 0; cc < 4; cc++)
                    acc[aa][cc] += a[aa] * w[cc];
        }
        __syncthreads();
    }

    int j = j0 + tx * 4;
    float4 bv = *(const float4*)(bias + j);
    #pragma unroll
    for (int aa = 0; aa < 4; aa++) {
        int i = i0 + ty * 4 + aa;
        float4 r = make_float4(acc[aa][0]+bv.x, acc[aa][1]+bv.y,
                               acc[aa][2]+bv.z, acc[aa][3]+bv.w);
        if (split == 1) {
            int b = i >> 12, il = i & (NQ-1);
            int h = j >> 6,  d  = j & (DH-1);
            *(float4*)(C + (((size_t)(b*NH + h)*NQ + il)*DH + d)) = r;
        } else {
            *(float4*)(C + (size_t)i * DM + j) = r;
        }
    }
}

// ===========================================================================
// mma.sync tf32 attention.
// CTA = 128 q rows of one (b,h); 8 warps as 4(m) x 2(n); K-tile 64.
// S = QK^T via m16n8k8 tf32 (Q frags in regs), P = exp(S/8) masked,
// P streamed to attn gmem (unnormalized), PV A-frags via quad shuffles,
// O accumulated in regs, cross-warp(n) O reduce at end, O /= rowsum.
// ===========================================================================
#define PITCH 68                 // floats per smem row (272B, 16B-multiple)
#define TILEB (64*PITCH*4)       // 17408 B per tile buffer
#define KOFF(buf)  ((buf)*TILEB)
#define VOFF(buf)  (2*TILEB + (buf)*TILEB)
#define LSUM_F     (4*TILEB/4)           // float index 17408
#define LINV_F     (LSUM_F + 256)
#define SM_BYTES   (4*TILEB + (256+128)*4)
#define NT         (NKK/64)              // 64 k-tiles

__global__ __launch_bounds__(256, 1) void attn_mma(
    const unsigned char* __restrict__ mask, float* __restrict__ attn)
{
    extern __shared__ float smf[];
    uint32_t sb = s2u(smf);

    int tid  = threadIdx.x;
    int w    = tid >> 5, lane = tid & 31;
    int wm   = w >> 1,  wn = w & 1;
    int g    = lane >> 2, t = lane & 3;

    int bh = blockIdx.x;               // bh fastest -> K/V L2 sharing
    int b  = bh >> 3, h = bh & 7;
    int q0 = blockIdx.y * 128;

    const float* qg = g_q + ((size_t)bh * NQ + q0) * DH;
    const float* kg = g_k + (size_t)bh * NKK * DH;
    const float* vg = g_v + (size_t)bh * NKK * DH;
    float* ab = attn + (size_t)(h * BB + b) * NQ * NKK;
    const unsigned char* mbase = mask + (size_t)b * NQ * NKK;

    // ---- stage Q into smem (reuses KV region before pipeline starts) ----
    #pragma unroll
    for (int i = 0; i < 8; i++) {
        int idx = tid + i * 256;           // 2048 float4
        int r = idx >> 4, c4 = (idx & 15) << 2;
        float4 v = *(const float4*)(qg + (size_t)r * DH + c4);
        *(float4*)(smf + r * PITCH + c4) = v;
    }
    __syncthreads();

    // ---- preload Q A-fragments (tf32) ----
    uint32_t qa[2][8][4];
    #pragma unroll
    for (int mb = 0; mb < 2; mb++) {
        int R = wm * 32 + mb * 16 + g;
        #pragma unroll
        for (int s = 0; s < 8; s++) {
            int c = s * 8 + t;
            qa[mb][s][0] = f2tf(smf[R * PITCH + c]);
            qa[mb][s][1] = f2tf(smf[(R + 8) * PITCH + c]);
            qa[mb][s][2] = f2tf(smf[R * PITCH + c + 4]);
            qa[mb][s][3] = f2tf(smf[(R + 8) * PITCH + c + 4]);
        }
    }
    __syncthreads();

    float oacc[2][8][4] = {};
    float lacc[2][2] = {};

    // ---- prologue: tile 0 ----
    {
        #pragma unroll
        for (int i = 0; i < 4; i++) {
            int c = tid + i * 256;              // 1024 chunks of 16B per tensor
            int r = c >> 4, c16 = c & 15;
            cpa16(sb + KOFF(0) + (uint32_t)(r * PITCH + c16 * 4) * 4,
                  kg + (size_t)r * DH + c16 * 4);
            cpa16(sb + VOFF(0) + (uint32_t)(r * PITCH + c16 * 4) * 4,
                  vg + (size_t)r * DH + c16 * 4);
        }
        CP_COMMIT();
    }

    for (int it = 0; it < NT; it++) {
        int buf = it & 1;
        if (it + 1 < NT) {
            int j0n = (it + 1) * 64, nb = buf ^ 1;
            #pragma unroll
            for (int i = 0; i < 4; i++) {
                int c = tid + i * 256;
                int r = c >> 4, c16 = c & 15;
                cpa16(sb + KOFF(nb) + (uint32_t)(r * PITCH + c16 * 4) * 4,
                      kg + (size_t)(j0n + r) * DH + c16 * 4);
                cpa16(sb + VOFF(nb) + (uint32_t)(r * PITCH + c16 * 4) * 4,
                      vg + (size_t)(j0n + r) * DH + c16 * 4);
            }
            CP_COMMIT();
            CP_WAIT(1);
        } else {
            CP_WAIT(0);
        }
        __syncthreads();

        const float* Ks = smf + KOFF(buf) / 4;
        const float* Vs = smf + VOFF(buf) / 4;

        // ---- QK^T ----
        float sacc[2][4][4] = {};
        #pragma unroll
        for (int s = 0; s < 8; s++) {
            #pragma unroll
            for (int j = 0; j < 4; j++) {
                int n0 = wn * 32 + j * 8;
                uint32_t b0 = __float_as_uint(Ks[(n0 + g) * PITCH + s * 8 + t]);
                uint32_t b1 = __float_as_uint(Ks[(n0 + g) * PITCH + s * 8 + t + 4]);
                mma8(sacc[0][j], qa[0][s], b0, b1);
                mma8(sacc[1][j], qa[1][s], b0, b1);
            }
        }

        // ---- epilogue + PV ----
        int jg0 = it * 64 + wn * 32;
        #pragma unroll
        for (int j = 0; j < 4; j++) {
            uint32_t pa[2][4];
            #pragma unroll
            for (int mb = 0; mb < 2; mb++) {
                int r0 = q0 + wm * 32 + mb * 16 + g;
                int colg = jg0 + j * 8 + 2 * t;
                const unsigned char* m0 = mbase + (size_t)r0 * NKK + colg;
                unsigned short mv0 = *(const unsigned short*)m0;
                unsigned short mv1 = *(const unsigned short*)(m0 + 8 * NKK);
                float* s4 = sacc[mb][j];
                float p0 = (mv0 & 0xff) ? 0.f : __expf(s4[0] * 0.125f);
                float p1 = (mv0 >> 8)   ? 0.f : __expf(s4[1] * 0.125f);
                float p2 = (mv1 & 0xff) ? 0.f : __expf(s4[2] * 0.125f);
                float p3 = (mv1 >> 8)   ? 0.f : __expf(s4[3] * 0.125f);
                lacc[mb][0] += p0 + p1;
                lacc[mb][1] += p2 + p3;
                __stcs((float2*)(ab + (size_t)r0 * NKK + colg), make_float2(p0, p1));
                __stcs((float2*)(ab + (size_t)(r0 + 8) * NKK + colg), make_float2(p2, p3));
                // C-frag -> A-frag permutation via quad shuffles
                int srcA = (lane & 28) | (t >> 1);
                float x0 = __shfl_sync(0xffffffffu, p0, srcA);
                float x1 = __shfl_sync(0xffffffffu, p1, srcA);
                float y0 = __shfl_sync(0xffffffffu, p0, srcA + 2);
                float y1 = __shfl_sync(0xffffffffu, p1, srcA + 2);
                float z0 = __shfl_sync(0xffffffffu, p2, srcA);
                float z1 = __shfl_sync(0xffffffffu, p3, srcA);
                float w0 = __shfl_sync(0xffffffffu, p2, srcA + 2);
                float w1 = __shfl_sync(0xffffffffu, p3, srcA + 2);
                pa[mb][0] = f2tf((t & 1) ? x1 : x0);
                pa[mb][1] = f2tf((t & 1) ? z1 : z0);
                pa[mb][2] = f2tf((t & 1) ? y1 : y0);
                pa[mb][3] = f2tf((t & 1) ? w1 : w0);
            }
            int k0 = wn * 32 + j * 8;
            #pragma unroll
            for (int jd = 0; jd < 8; jd++) {
                uint32_t b0 = __float_as_uint(Vs[(k0 + t) * PITCH + jd * 8 + g]);
                uint32_t b1 = __float_as_uint(Vs[(k0 + t + 4) * PITCH + jd * 8 + g]);
                mma8(oacc[0][jd], pa[0], b0, b1);
                mma8(oacc[1][jd], pa[1], b0, b1);
            }
        }
        __syncthreads();
    }

    // ---- rowsum reduce ----
    #pragma unroll
    for (int off = 1; off <= 2; off <<= 1) {
        #pragma unroll
        for (int mb = 0; mb < 2; mb++) {
            lacc[mb][0] += __shfl_xor_sync(0xffffffffu, lacc[mb][0], off);
            lacc[mb][1] += __shfl_xor_sync(0xffffffffu, lacc[mb][1], off);
        }
    }
    float* lsum = smf + LSUM_F;
    float* linv = smf + LINV_F;
    if (t == 0) {
        #pragma unroll
        for (int mb = 0; mb < 2; mb++) {
            lsum[wn * 128 + wm * 32 + mb * 16 + g]     = lacc[mb][0];
            lsum[wn * 128 + wm * 32 + mb * 16 + g + 8] = lacc[mb][1];
        }
    }
    __syncthreads();
    if (tid < 128) {
        float tot = lsum[tid] + lsum[128 + tid];
        g_l[(size_t)bh * NQ + q0 + tid] = tot;
        linv[tid] = 1.0f / tot;
    }
    __syncthreads();

    // ---- cross-warp(n) O reduction via smem (reuse KV region) ----
    if (wn == 1) {
        #pragma unroll
        for (int mb = 0; mb < 2; mb++) {
            int r = wm * 32 + mb * 16 + g;
            #pragma unroll
            for (int jd = 0; jd < 8; jd++) {
                *(float2*)(smf + r * PITCH + jd * 8 + 2 * t) =
                    make_float2(oacc[mb][jd][0], oacc[mb][jd][1]);
                *(float2*)(smf + (r + 8) * PITCH + jd * 8 + 2 * t) =
                    make_float2(oacc[mb][jd][2], oacc[mb][jd][3]);
            }
        }
    }
    __syncthreads();
    if (wn == 0) {
        #pragma unroll
        for (int mb = 0; mb < 2; mb++) {
            int r = wm * 32 + mb * 16 + g;
            float i0v = linv[r], i1v = linv[r + 8];
            float* og0 = g_o + (size_t)(b * NQ + q0 + r) * DM + h * DH;
            float* og1 = og0 + 8 * DM;
            #pragma unroll
            for (int jd = 0; jd < 8; jd++) {
                float2 e0 = *(float2*)(smf + r * PITCH + jd * 8 + 2 * t);
                float2 e1 = *(float2*)(smf + (r + 8) * PITCH + jd * 8 + 2 * t);
                *(float2*)(og0 + jd * 8 + 2 * t) = make_float2(
                    (oacc[mb][jd][0] + e0.x) * i0v, (oacc[mb][jd][1] + e0.y) * i0v);
                *(float2*)(og1 + jd * 8 + 2 * t) = make_float2(
                    (oacc[mb][jd][2] + e1.x) * i1v, (oacc[mb][jd][3] + e1.y) * i1v);
            }
        }
    }
}

// ===========================================================================
// Streaming normalize: attn[h,b,i,:] /= l[b,h,i]
// ===========================================================================
__global__ __launch_bounds__(256) void norm_attn(float* __restrict__ attn)
{
    size_t idx = (size_t)blockIdx.x * blockDim.x + threadIdx.x;
    size_t rowi = idx >> 10;
    int i  = (int)(rowi & (NQ - 1));
    int hb = (int)(rowi >> 12);
    int h = hb >> 1, b = hb & 1;
    float inv = 1.0f / g_l[(size_t)(b * NH + h) * NQ + i];
    float4 v = __ldcs((const float4*)attn + idx);
    v.x *= inv; v.y *= inv; v.z *= inv; v.w *= inv;
    __stcs((float4*)attn + idx, v);
}

extern "C" void kernel_launch(void* const* d_in, const int* in_sizes, int n_in,
                              void* d_out, int out_size)
{
    const float* q  = (const float*)d_in[0];
    const float* k  = (const float*)d_in[1];
    const float* v  = (const float*)d_in[2];
    const unsigned char* mask = (const unsigned char*)d_in[3];
    const float* Wq = (const float*)d_in[4];
    const float* bq = (const float*)d_in[5];
    const float* Wk = (const float*)d_in[6];
    const float* bk = (const float*)d_in[7];
    const float* Wv = (const float*)d_in[8];
    const float* bv = (const float*)d_in[9];
    const float* Wo = (const float*)d_in[10];
    const float* bo = (const float*)d_in[11];

    float* outbuf = (float*)d_out;
    float* attn = outbuf;
    float* outp = outbuf + ATTN_ELEMS;

    float *gq, *gk, *gv, *go;
    cudaGetSymbolAddress((void**)&gq, g_q);
    cudaGetSymbolAddress((void**)&gk, g_k);
    cudaGetSymbolAddress((void**)&gv, g_v);
    cudaGetSymbolAddress((void**)&go, g_o);

    dim3 blk(16, 16);
    dim3 gproj(DM / 64, MROWS / 64);

    gemm_nt<<<gproj, blk>>>(q, Wq, bq, gq, 1);
    gemm_nt<<<gproj, blk>>>(k, Wk, bk, gk, 1);
    gemm_nt<<<gproj, blk>>>(v, Wv, bv, gv, 1);

    cudaFuncSetAttribute(attn_mma,
        cudaFuncAttributeMaxDynamicSharedMemorySize, SM_BYTES);
    attn_mma<<<dim3(BB * NH, NQ / 128), 256, SM_BYTES>>>(mask, attn);

    norm_attn<<<(unsigned)(ATTN_ELEMS / 4 / 256), 256>>>(attn);

    gemm_nt<<<gproj, blk>>>(go, Wo, bo, outp, 0);
}